// round 3
// baseline (speedup 1.0000x reference)
#include <cuda_runtime.h>
#include <math.h>
#include <stdint.h>

// MemoryCrossAttention: B=4, L=4096, M=256, H=2048, NH=16, HD=128
// Round-3: tf32 mma.sync GEMMs + fused attention, PLUS:
//  - size-based input resolution (handles dict-order AND alphabetical metadata)
//  - device-side mask dtype detection (uint8 / int32 / float32) -> normalized u8

#define B_  4
#define L_  4096
#define M_  256
#define H_  2048
#define NH_ 16
#define HD_ 128
#define EPS_ 1e-6f
#define SCALE_ 0.08838834764831845f   // HD^-0.5

// ---------------- scratch (static __device__, no allocations) ----------------
__device__ float g_x[(size_t)B_ * L_ * H_];   // rmsnorm output
__device__ float g_q[(size_t)B_ * L_ * H_];   // q projection
__device__ float g_g[(size_t)B_ * L_ * H_];   // gate logits
__device__ float g_a[(size_t)B_ * L_ * H_];   // attention output (pre-Wo)
__device__ float g_k[(size_t)B_ * M_ * H_];
__device__ float g_v[(size_t)B_ * M_ * H_];
__device__ unsigned char g_mask[B_ * M_];     // normalized mask

// ---------------- helpers ----------------------------------------------------
__device__ __forceinline__ uint32_t f2tf32(float v) {
    uint32_t r;
    asm("cvt.rna.tf32.f32 %0, %1;" : "=r"(r) : "f"(v));
    return r;
}

__device__ __forceinline__ void mma_tf32(float c[4], const uint32_t a[4],
                                         const uint32_t b[2]) {
    asm volatile(
        "mma.sync.aligned.m16n8k8.row.col.f32.tf32.tf32.f32 "
        "{%0,%1,%2,%3}, {%4,%5,%6,%7}, {%8,%9}, {%0,%1,%2,%3};"
        : "+f"(c[0]), "+f"(c[1]), "+f"(c[2]), "+f"(c[3])
        : "r"(a[0]), "r"(a[1]), "r"(a[2]), "r"(a[3]), "r"(b[0]), "r"(b[1]));
}

// ---------------- mask normalize: detect dtype, write u8 ---------------------
// uint8 mask: 1024 bytes of 0/1. int32 mask: 4096 bytes, words 0/1.
// float32 mask: 4096 bytes, words 0 / 0x3f800000. Detection over the first
// 1024 bytes (valid under every interpretation):
//   any byte > 1                         -> float32
//   any nonzero byte at offset%4 != 0    -> uint8
//   else                                 -> int32
__global__ __launch_bounds__(256) void mask_normalize_kernel(
    const void* __restrict__ mraw, unsigned char* __restrict__ mout) {
    const uint32_t* w = (const uint32_t*)mraw;
    int tid = threadIdx.x;
    uint32_t word = w[tid];  // bytes 4*tid .. 4*tid+3 of the first 1024
    int big = 0, odd = 0;
#pragma unroll
    for (int byi = 0; byi < 4; byi++) {
        uint32_t by = (word >> (byi * 8)) & 0xffu;
        if (by > 1u) big = 1;
        if (byi != 0 && by != 0u) odd = 1;
    }
    int any_big = __syncthreads_or(big);
    int any_odd = __syncthreads_or(odd);

    // 256 threads x 4 entries = 1024 mask entries
#pragma unroll
    for (int i = 0; i < 4; i++) {
        int m = tid * 4 + i;
        unsigned char val;
        if (any_big) {               // float32
            val = (((const float*)mraw)[m] != 0.0f) ? 1 : 0;
        } else if (any_odd) {        // uint8
            val = ((const unsigned char*)mraw)[m] ? 1 : 0;
        } else {                     // int32
            val = (((const int*)mraw)[m] != 0) ? 1 : 0;
        }
        mout[m] = val;
    }
}

// ---------------- rmsnorm: one block (256 thr) per row of H=2048 -------------
__global__ __launch_bounds__(256) void rmsnorm_kernel(
    const float* __restrict__ in, const float* __restrict__ w,
    float* __restrict__ out) {
    size_t row = blockIdx.x;
    const float* x = in + row * H_;
    float* y = out + row * H_;
    int tid = threadIdx.x;

    float4 a = *(const float4*)&x[tid * 4];
    float4 b = *(const float4*)&x[1024 + tid * 4];
    float ss = a.x * a.x + a.y * a.y + a.z * a.z + a.w * a.w
             + b.x * b.x + b.y * b.y + b.z * b.z + b.w * b.w;
#pragma unroll
    for (int o = 16; o; o >>= 1) ss += __shfl_xor_sync(0xffffffffu, ss, o);
    __shared__ float sw[8];
    if ((tid & 31) == 0) sw[tid >> 5] = ss;
    __syncthreads();
    float tot = sw[0] + sw[1] + sw[2] + sw[3] + sw[4] + sw[5] + sw[6] + sw[7];
    float inv = rsqrtf(tot * (1.0f / H_) + EPS_);

    float4 wa = *(const float4*)&w[tid * 4];
    float4 wb = *(const float4*)&w[1024 + tid * 4];
    a.x *= inv * wa.x; a.y *= inv * wa.y; a.z *= inv * wa.z; a.w *= inv * wa.w;
    b.x *= inv * wb.x; b.y *= inv * wb.y; b.z *= inv * wb.z; b.w *= inv * wb.w;
    *(float4*)&y[tid * 4] = a;
    *(float4*)&y[1024 + tid * 4] = b;
}

// ---------------- tf32 GEMM: C[M,N] = A[M,K] @ B[N,K]^T ----------------------
// Block 128x128, 8 warps in 2x4, warp tile 64x32, m16n8k8 tf32 atoms.
// Optional epilogue C = sigmoid(G) * C.
#define TBM 128
#define TBN 128
#define TBK 16
#define TPAD 4   // smem row stride = 20 words -> conflict-free quad access

__global__ __launch_bounds__(256) void gemm_tf32_nt(
    const float* __restrict__ A, const float* __restrict__ Bm,
    float* __restrict__ C, const float* __restrict__ G,
    int M, int N, int K) {
    __shared__ uint32_t As[TBM][TBK + TPAD];
    __shared__ uint32_t Bs[TBN][TBK + TPAD];
    int bm = blockIdx.y * TBM;
    int bn = blockIdx.x * TBN;
    int tid = threadIdx.x;
    int lane = tid & 31;
    int warp = tid >> 5;
    int wm = warp >> 2;   // 0..1 -> 64-row slab
    int wn = warp & 3;    // 0..3 -> 32-col slab

    float acc[4][4][4];
#pragma unroll
    for (int i = 0; i < 4; i++)
#pragma unroll
        for (int j = 0; j < 4; j++)
#pragma unroll
            for (int t = 0; t < 4; t++) acc[i][j][t] = 0.0f;

    int lq = lane & 3;    // k within fragment
    int lg = lane >> 2;   // row/col group within atom

    for (int k0 = 0; k0 < K; k0 += TBK) {
#pragma unroll
        for (int i = 0; i < 2; i++) {
            int idx = tid * 2 + i;
            int row = idx >> 2;
            int kq = (idx & 3) << 2;
            float4 va = *(const float4*)&A[(size_t)(bm + row) * K + k0 + kq];
            *(uint4*)&As[row][kq] =
                make_uint4(f2tf32(va.x), f2tf32(va.y), f2tf32(va.z), f2tf32(va.w));
            float4 vb = *(const float4*)&Bm[(size_t)(bn + row) * K + k0 + kq];
            *(uint4*)&Bs[row][kq] =
                make_uint4(f2tf32(vb.x), f2tf32(vb.y), f2tf32(vb.z), f2tf32(vb.w));
        }
        __syncthreads();

#pragma unroll
        for (int kk = 0; kk < TBK; kk += 8) {
            uint32_t af[4][4];
            uint32_t bf[4][2];
#pragma unroll
            for (int am = 0; am < 4; am++) {
                int r = wm * 64 + am * 16 + lg;
                af[am][0] = As[r][kk + lq];
                af[am][1] = As[r + 8][kk + lq];
                af[am][2] = As[r][kk + lq + 4];
                af[am][3] = As[r + 8][kk + lq + 4];
            }
#pragma unroll
            for (int bj = 0; bj < 4; bj++) {
                int cidx = wn * 32 + bj * 8 + lg;
                bf[bj][0] = Bs[cidx][kk + lq];
                bf[bj][1] = Bs[cidx][kk + lq + 4];
            }
#pragma unroll
            for (int am = 0; am < 4; am++)
#pragma unroll
                for (int bj = 0; bj < 4; bj++)
                    mma_tf32(acc[am][bj], af[am], bf[bj]);
        }
        __syncthreads();
    }

#pragma unroll
    for (int am = 0; am < 4; am++) {
        size_t row0 = (size_t)(bm + wm * 64 + am * 16 + lg);
#pragma unroll
        for (int bj = 0; bj < 4; bj++) {
            size_t col = (size_t)(bn + wn * 32 + bj * 8 + lq * 2);
            float2 p0 = make_float2(acc[am][bj][0], acc[am][bj][1]);
            float2 p1 = make_float2(acc[am][bj][2], acc[am][bj][3]);
            if (G != nullptr) {
                float2 g0 = *(const float2*)&G[row0 * (size_t)N + col];
                float2 g1 = *(const float2*)&G[(row0 + 8) * (size_t)N + col];
                p0.x *= 1.0f / (1.0f + __expf(-g0.x));
                p0.y *= 1.0f / (1.0f + __expf(-g0.y));
                p1.x *= 1.0f / (1.0f + __expf(-g1.x));
                p1.y *= 1.0f / (1.0f + __expf(-g1.y));
            }
            *(float2*)&C[row0 * (size_t)N + col] = p0;
            *(float2*)&C[(row0 + 8) * (size_t)N + col] = p1;
        }
    }
}

// ---------------- attention: per (b,h), 16 L-rows per block ------------------
#define AT_TL 16
#define AT_MC 32

__global__ __launch_bounds__(256) void attn_kernel(
    const float* __restrict__ q, const float* __restrict__ k,
    const float* __restrict__ v, const unsigned char* __restrict__ mask,
    float* __restrict__ out) {
    __shared__ float Qs[AT_TL][HD_ + 4];
    __shared__ float KVs[AT_MC][HD_ + 4];
    __shared__ float Ss[AT_TL][M_];

    int b = blockIdx.z;
    int h = blockIdx.y;
    int l0 = blockIdx.x * AT_TL;
    int tid = threadIdx.x;

#pragma unroll
    for (int i = 0; i < 2; i++) {
        int idx = tid * 2 + i;
        int r = idx >> 5;
        int c = (idx & 31) << 2;
        *(float4*)&Qs[r][c] =
            *(const float4*)&q[((size_t)(b * L_ + l0 + r)) * H_ + h * HD_ + c];
    }

    int r = tid & 15;       // L-row within tile
    int mg = tid >> 4;      // 0..15: m-lane within chunk
    for (int c0 = 0; c0 < M_; c0 += AT_MC) {
        __syncthreads();
#pragma unroll
        for (int i = 0; i < 4; i++) {
            int idx = tid * 4 + i;
            int rr = idx >> 5;
            int cc = (idx & 31) << 2;
            *(float4*)&KVs[rr][cc] =
                *(const float4*)&k[((size_t)(b * M_ + c0 + rr)) * H_ + h * HD_ + cc];
        }
        __syncthreads();
        float s0 = 0.0f, s1 = 0.0f;
#pragma unroll
        for (int d = 0; d < HD_; d += 4) {
            float4 qv = *(float4*)&Qs[r][d];
            float4 k0v = *(float4*)&KVs[mg][d];
            float4 k1v = *(float4*)&KVs[mg + 16][d];
            s0 += qv.x * k0v.x + qv.y * k0v.y + qv.z * k0v.z + qv.w * k0v.w;
            s1 += qv.x * k1v.x + qv.y * k1v.y + qv.z * k1v.z + qv.w * k1v.w;
        }
        int m0 = c0 + mg, m1 = c0 + mg + 16;
        Ss[r][m0] = mask[b * M_ + m0] ? s0 * SCALE_ : -INFINITY;
        Ss[r][m1] = mask[b * M_ + m1] ? s1 * SCALE_ : -INFINITY;
    }
    __syncthreads();

    int warp = tid >> 5, lane = tid & 31;
#pragma unroll
    for (int rep = 0; rep < 2; rep++) {
        int rr = warp + rep * 8;
        float sv[8];
        float mx = -INFINITY;
#pragma unroll
        for (int j = 0; j < 8; j++) {
            sv[j] = Ss[rr][lane + j * 32];
            mx = fmaxf(mx, sv[j]);
        }
#pragma unroll
        for (int o = 16; o; o >>= 1) mx = fmaxf(mx, __shfl_xor_sync(0xffffffffu, mx, o));
        float sum = 0.0f;
#pragma unroll
        for (int j = 0; j < 8; j++) {
            float e = (mx > -INFINITY) ? __expf(sv[j] - mx) : 0.0f;
            sv[j] = e;
            sum += e;
        }
#pragma unroll
        for (int o = 16; o; o >>= 1) sum += __shfl_xor_sync(0xffffffffu, sum, o);
        float inv = (sum > 0.0f) ? (1.0f / sum) : 0.0f;
#pragma unroll
        for (int j = 0; j < 8; j++) Ss[rr][lane + j * 32] = sv[j] * inv;
    }

    int ro = tid >> 4;
    int d0 = (tid & 15) << 3;
    float acc[8] = {0, 0, 0, 0, 0, 0, 0, 0};
    for (int c0 = 0; c0 < M_; c0 += AT_MC) {
        __syncthreads();
#pragma unroll
        for (int i = 0; i < 4; i++) {
            int idx = tid * 4 + i;
            int rr = idx >> 5;
            int cc = (idx & 31) << 2;
            *(float4*)&KVs[rr][cc] =
                *(const float4*)&v[((size_t)(b * M_ + c0 + rr)) * H_ + h * HD_ + cc];
        }
        __syncthreads();
#pragma unroll
        for (int m = 0; m < AT_MC; m++) {
            float p = Ss[ro][c0 + m];
            float4 v0 = *(float4*)&KVs[m][d0];
            float4 v1 = *(float4*)&KVs[m][d0 + 4];
            acc[0] += p * v0.x; acc[1] += p * v0.y;
            acc[2] += p * v0.z; acc[3] += p * v0.w;
            acc[4] += p * v1.x; acc[5] += p * v1.y;
            acc[6] += p * v1.z; acc[7] += p * v1.w;
        }
    }
    size_t obase = ((size_t)(b * L_ + l0 + ro)) * H_ + h * HD_ + d0;
    *(float4*)&out[obase] = make_float4(acc[0], acc[1], acc[2], acc[3]);
    *(float4*)&out[obase + 4] = make_float4(acc[4], acc[5], acc[6], acc[7]);
}

// ---------------- launch --------------------------------------------------
extern "C" void kernel_launch(void* const* d_in, const int* in_sizes, int n_in,
                              void* d_out, int out_size) {
    // Resolve inputs by element count (robust to metadata ordering).
    const size_t SZ_HID = (size_t)B_ * L_ * H_;   // 33554432
    const size_t SZ_MEM = (size_t)B_ * M_ * H_;   // 2097152
    const size_t SZ_MSK = (size_t)B_ * M_;        // 1024
    const size_t SZ_NRM = (size_t)H_;             // 2048
    const size_t SZ_W   = (size_t)H_ * H_;        // 4194304

    int i_hid = 0, i_mem = 1, i_msk = 2, i_nrm = 3;
    int wi[5] = {4, 5, 6, 7, 8};
    int nw = 0;
    for (int i = 0; i < n_in; i++) {
        size_t s = (size_t)in_sizes[i];
        if (s == SZ_HID) i_hid = i;
        else if (s == SZ_MEM) i_mem = i;
        else if (s == SZ_MSK) i_msk = i;
        else if (s == SZ_NRM) i_nrm = i;
        else if (s == SZ_W && nw < 5) wi[nw++] = i;
    }
    // Weight identity depends on serialization convention:
    //  dict order       : wq, wk, wv, wo, wg  (mask AFTER memory_tokens)
    //  alphabetical     : wg, wk, wo, wq, wv  (mask BEFORE memory_tokens)
    int iq, ik, iv, io, ig;
    if (i_msk < i_mem) { ig = wi[0]; ik = wi[1]; io = wi[2]; iq = wi[3]; iv = wi[4]; }
    else               { iq = wi[0]; ik = wi[1]; iv = wi[2]; io = wi[3]; ig = wi[4]; }

    const float* hidden = (const float*)d_in[i_hid];
    const float* memtok = (const float*)d_in[i_mem];
    const void*  mraw   = d_in[i_msk];
    const float* normw  = (const float*)d_in[i_nrm];
    const float* wq = (const float*)d_in[iq];
    const float* wk = (const float*)d_in[ik];
    const float* wv = (const float*)d_in[iv];
    const float* wo = (const float*)d_in[io];
    const float* wg = (const float*)d_in[ig];
    float* out = (float*)d_out;

    float *x, *q, *g, *a, *kb, *vb;
    unsigned char* mnorm;
    cudaGetSymbolAddress((void**)&x, g_x);
    cudaGetSymbolAddress((void**)&q, g_q);
    cudaGetSymbolAddress((void**)&g, g_g);
    cudaGetSymbolAddress((void**)&a, g_a);
    cudaGetSymbolAddress((void**)&kb, g_k);
    cudaGetSymbolAddress((void**)&vb, g_v);
    cudaGetSymbolAddress((void**)&mnorm, g_mask);

    // 0. normalize mask (dtype auto-detect)
    mask_normalize_kernel<<<1, 256>>>(mraw, mnorm);

    // 1. x = rmsnorm(hidden)
    rmsnorm_kernel<<<B_ * L_, 256>>>(hidden, normw, x);

    dim3 gbig(H_ / TBN, (B_ * L_) / TBM);   // 16 x 128
    dim3 gsmall(H_ / TBN, (B_ * M_) / TBM); // 16 x 8

    // 2-5. projections (tf32 tensor cores)
    gemm_tf32_nt<<<gbig, 256>>>(x, wq, q, nullptr, B_ * L_, H_, H_);
    gemm_tf32_nt<<<gsmall, 256>>>(memtok, wk, kb, nullptr, B_ * M_, H_, H_);
    gemm_tf32_nt<<<gsmall, 256>>>(memtok, wv, vb, nullptr, B_ * M_, H_, H_);
    gemm_tf32_nt<<<gbig, 256>>>(x, wg, g, nullptr, B_ * L_, H_, H_);

    // 6. attention
    attn_kernel<<<dim3(L_ / AT_TL, NH_, B_), 256>>>(q, kb, vb, mnorm, a);

    // 7. out = sigmoid(g) * (a @ Wo^T)   (gate fused in epilogue)
    gemm_tf32_nt<<<gbig, 256>>>(a, wo, out, g, B_ * L_, H_, H_);
}

// round 4
// speedup vs baseline: 1.1124x; 1.1124x over previous
#include <cuda_runtime.h>
#include <math.h>
#include <stdint.h>

// MemoryCrossAttention: B=4, L=4096, M=256, H=2048, NH=16, HD=128
// Round-4: cp.async double-buffered tf32 GEMM pipeline (2-stage), tf32 cvt
// moved to fragment load, 2 CTAs/SM. Attention/rmsnorm unchanged from R3.

#define B_  4
#define L_  4096
#define M_  256
#define H_  2048
#define NH_ 16
#define HD_ 128
#define EPS_ 1e-6f
#define SCALE_ 0.08838834764831845f   // HD^-0.5

// ---------------- scratch (static __device__, no allocations) ----------------
__device__ float g_x[(size_t)B_ * L_ * H_];
__device__ float g_q[(size_t)B_ * L_ * H_];
__device__ float g_g[(size_t)B_ * L_ * H_];
__device__ float g_a[(size_t)B_ * L_ * H_];
__device__ float g_k[(size_t)B_ * M_ * H_];
__device__ float g_v[(size_t)B_ * M_ * H_];
__device__ unsigned char g_mask[B_ * M_];

// ---------------- helpers ----------------------------------------------------
__device__ __forceinline__ uint32_t f2tf32(float v) {
    uint32_t r;
    asm("cvt.rna.tf32.f32 %0, %1;" : "=r"(r) : "f"(v));
    return r;
}

__device__ __forceinline__ void mma_tf32(float c[4], const uint32_t a[4],
                                         const uint32_t b[2]) {
    asm volatile(
        "mma.sync.aligned.m16n8k8.row.col.f32.tf32.tf32.f32 "
        "{%0,%1,%2,%3}, {%4,%5,%6,%7}, {%8,%9}, {%0,%1,%2,%3};"
        : "+f"(c[0]), "+f"(c[1]), "+f"(c[2]), "+f"(c[3])
        : "r"(a[0]), "r"(a[1]), "r"(a[2]), "r"(a[3]), "r"(b[0]), "r"(b[1]));
}

__device__ __forceinline__ void cp16(void* smem_dst, const void* gptr) {
    uint32_t s = (uint32_t)__cvta_generic_to_shared(smem_dst);
    asm volatile("cp.async.cg.shared.global [%0], [%1], 16;\n"
                 :: "r"(s), "l"(gptr));
}
__device__ __forceinline__ void cp_commit() {
    asm volatile("cp.async.commit_group;\n");
}
template <int N>
__device__ __forceinline__ void cp_wait() {
    asm volatile("cp.async.wait_group %0;\n" :: "n"(N));
}

// ---------------- mask normalize: detect dtype, write u8 ---------------------
__global__ __launch_bounds__(256) void mask_normalize_kernel(
    const void* __restrict__ mraw, unsigned char* __restrict__ mout) {
    const uint32_t* w = (const uint32_t*)mraw;
    int tid = threadIdx.x;
    uint32_t word = w[tid];
    int big = 0, odd = 0;
#pragma unroll
    for (int byi = 0; byi < 4; byi++) {
        uint32_t by = (word >> (byi * 8)) & 0xffu;
        if (by > 1u) big = 1;
        if (byi != 0 && by != 0u) odd = 1;
    }
    int any_big = __syncthreads_or(big);
    int any_odd = __syncthreads_or(odd);
#pragma unroll
    for (int i = 0; i < 4; i++) {
        int m = tid * 4 + i;
        unsigned char val;
        if (any_big)      val = (((const float*)mraw)[m] != 0.0f) ? 1 : 0;
        else if (any_odd) val = ((const unsigned char*)mraw)[m] ? 1 : 0;
        else              val = (((const int*)mraw)[m] != 0) ? 1 : 0;
        mout[m] = val;
    }
}

// ---------------- rmsnorm ----------------------------------------------------
__global__ __launch_bounds__(256) void rmsnorm_kernel(
    const float* __restrict__ in, const float* __restrict__ w,
    float* __restrict__ out) {
    size_t row = blockIdx.x;
    const float* x = in + row * H_;
    float* y = out + row * H_;
    int tid = threadIdx.x;

    float4 a = *(const float4*)&x[tid * 4];
    float4 b = *(const float4*)&x[1024 + tid * 4];
    float ss = a.x * a.x + a.y * a.y + a.z * a.z + a.w * a.w
             + b.x * b.x + b.y * b.y + b.z * b.z + b.w * b.w;
#pragma unroll
    for (int o = 16; o; o >>= 1) ss += __shfl_xor_sync(0xffffffffu, ss, o);
    __shared__ float sw[8];
    if ((tid & 31) == 0) sw[tid >> 5] = ss;
    __syncthreads();
    float tot = sw[0] + sw[1] + sw[2] + sw[3] + sw[4] + sw[5] + sw[6] + sw[7];
    float inv = rsqrtf(tot * (1.0f / H_) + EPS_);

    float4 wa = *(const float4*)&w[tid * 4];
    float4 wb = *(const float4*)&w[1024 + tid * 4];
    a.x *= inv * wa.x; a.y *= inv * wa.y; a.z *= inv * wa.z; a.w *= inv * wa.w;
    b.x *= inv * wb.x; b.y *= inv * wb.y; b.z *= inv * wb.z; b.w *= inv * wb.w;
    *(float4*)&y[tid * 4] = a;
    *(float4*)&y[1024 + tid * 4] = b;
}

// ---------------- tf32 GEMM with cp.async double buffering -------------------
// C[M,N] = A[M,K] @ B[N,K]^T. Block 128x128, 8 warps (2x4), warp 64x32.
// Smem holds raw fp32 (cp.async); cvt to tf32 at fragment load.
#define TBM 128
#define TBN 128
#define TBK 16
#define TST 20   // row stride in words (16 + 4 pad): conflict-free frag reads

__global__ __launch_bounds__(256, 2) void gemm_tf32_nt(
    const float* __restrict__ A, const float* __restrict__ Bm,
    float* __restrict__ C, const float* __restrict__ G,
    int M, int N, int K) {
    __shared__ float As[2][TBM][TST];
    __shared__ float Bs[2][TBN][TST];
    int bm = blockIdx.y * TBM;
    int bn = blockIdx.x * TBN;
    int tid = threadIdx.x;
    int lane = tid & 31;
    int warp = tid >> 5;
    int wm = warp >> 2;
    int wn = warp & 3;

    float acc[4][4][4];
#pragma unroll
    for (int i = 0; i < 4; i++)
#pragma unroll
        for (int j = 0; j < 4; j++)
#pragma unroll
            for (int t = 0; t < 4; t++) acc[i][j][t] = 0.0f;

    int lq = lane & 3;
    int lg = lane >> 2;

    // Per-thread load coords: 2 x 16B chunks of A and of B per tile.
    int r0 = (tid * 2) >> 2;          // row of chunk 0
    int c0q = ((tid * 2) & 3) << 2;   // k-quad of chunk 0
    int r1 = (tid * 2 + 1) >> 2;
    int c1q = ((tid * 2 + 1) & 3) << 2;

    const int nt = K / TBK;

    // Prefetch tile 0 into stage 0.
    {
        cp16(&As[0][r0][c0q], &A[(size_t)(bm + r0) * K + c0q]);
        cp16(&Bs[0][r0][c0q], &Bm[(size_t)(bn + r0) * K + c0q]);
        cp16(&As[0][r1][c1q], &A[(size_t)(bm + r1) * K + c1q]);
        cp16(&Bs[0][r1][c1q], &Bm[(size_t)(bn + r1) * K + c1q]);
        cp_commit();
    }

    for (int t = 0; t < nt; t++) {
        int cur = t & 1;
        if (t + 1 < nt) {
            int nxt = (t + 1) & 1;
            int k0 = (t + 1) * TBK;
            cp16(&As[nxt][r0][c0q], &A[(size_t)(bm + r0) * K + k0 + c0q]);
            cp16(&Bs[nxt][r0][c0q], &Bm[(size_t)(bn + r0) * K + k0 + c0q]);
            cp16(&As[nxt][r1][c1q], &A[(size_t)(bm + r1) * K + k0 + c1q]);
            cp16(&Bs[nxt][r1][c1q], &Bm[(size_t)(bn + r1) * K + k0 + c1q]);
            cp_commit();
            cp_wait<1>();   // current tile complete; next still in flight
        } else {
            cp_wait<0>();
        }
        __syncthreads();

#pragma unroll
        for (int kk = 0; kk < TBK; kk += 8) {
            uint32_t af[4][4];
            uint32_t bf[4][2];
#pragma unroll
            for (int am = 0; am < 4; am++) {
                int r = wm * 64 + am * 16 + lg;
                af[am][0] = f2tf32(As[cur][r][kk + lq]);
                af[am][1] = f2tf32(As[cur][r + 8][kk + lq]);
                af[am][2] = f2tf32(As[cur][r][kk + lq + 4]);
                af[am][3] = f2tf32(As[cur][r + 8][kk + lq + 4]);
            }
#pragma unroll
            for (int bj = 0; bj < 4; bj++) {
                int cidx = wn * 32 + bj * 8 + lg;
                bf[bj][0] = f2tf32(Bs[cur][cidx][kk + lq]);
                bf[bj][1] = f2tf32(Bs[cur][cidx][kk + lq + 4]);
            }
#pragma unroll
            for (int am = 0; am < 4; am++)
#pragma unroll
                for (int bj = 0; bj < 4; bj++)
                    mma_tf32(acc[am][bj], af[am], bf[bj]);
        }
        __syncthreads();   // stage `cur` free for reuse at t+2
    }

#pragma unroll
    for (int am = 0; am < 4; am++) {
        size_t row0 = (size_t)(bm + wm * 64 + am * 16 + lg);
#pragma unroll
        for (int bj = 0; bj < 4; bj++) {
            size_t col = (size_t)(bn + wn * 32 + bj * 8 + lq * 2);
            float2 p0 = make_float2(acc[am][bj][0], acc[am][bj][1]);
            float2 p1 = make_float2(acc[am][bj][2], acc[am][bj][3]);
            if (G != nullptr) {
                float2 g0 = *(const float2*)&G[row0 * (size_t)N + col];
                float2 g1 = *(const float2*)&G[(row0 + 8) * (size_t)N + col];
                p0.x *= 1.0f / (1.0f + __expf(-g0.x));
                p0.y *= 1.0f / (1.0f + __expf(-g0.y));
                p1.x *= 1.0f / (1.0f + __expf(-g1.x));
                p1.y *= 1.0f / (1.0f + __expf(-g1.y));
            }
            *(float2*)&C[row0 * (size_t)N + col] = p0;
            *(float2*)&C[(row0 + 8) * (size_t)N + col] = p1;
        }
    }
}

// ---------------- attention: per (b,h), 16 L-rows per block ------------------
#define AT_TL 16
#define AT_MC 32

__global__ __launch_bounds__(256) void attn_kernel(
    const float* __restrict__ q, const float* __restrict__ k,
    const float* __restrict__ v, const unsigned char* __restrict__ mask,
    float* __restrict__ out) {
    __shared__ float Qs[AT_TL][HD_ + 4];
    __shared__ float KVs[AT_MC][HD_ + 4];
    __shared__ float Ss[AT_TL][M_];

    int b = blockIdx.z;
    int h = blockIdx.y;
    int l0 = blockIdx.x * AT_TL;
    int tid = threadIdx.x;

#pragma unroll
    for (int i = 0; i < 2; i++) {
        int idx = tid * 2 + i;
        int r = idx >> 5;
        int c = (idx & 31) << 2;
        *(float4*)&Qs[r][c] =
            *(const float4*)&q[((size_t)(b * L_ + l0 + r)) * H_ + h * HD_ + c];
    }

    int r = tid & 15;
    int mg = tid >> 4;
    for (int c0 = 0; c0 < M_; c0 += AT_MC) {
        __syncthreads();
#pragma unroll
        for (int i = 0; i < 4; i++) {
            int idx = tid * 4 + i;
            int rr = idx >> 5;
            int cc = (idx & 31) << 2;
            *(float4*)&KVs[rr][cc] =
                *(const float4*)&k[((size_t)(b * M_ + c0 + rr)) * H_ + h * HD_ + cc];
        }
        __syncthreads();
        float s0 = 0.0f, s1 = 0.0f;
#pragma unroll
        for (int d = 0; d < HD_; d += 4) {
            float4 qv = *(float4*)&Qs[r][d];
            float4 k0v = *(float4*)&KVs[mg][d];
            float4 k1v = *(float4*)&KVs[mg + 16][d];
            s0 += qv.x * k0v.x + qv.y * k0v.y + qv.z * k0v.z + qv.w * k0v.w;
            s1 += qv.x * k1v.x + qv.y * k1v.y + qv.z * k1v.z + qv.w * k1v.w;
        }
        int m0 = c0 + mg, m1 = c0 + mg + 16;
        Ss[r][m0] = mask[b * M_ + m0] ? s0 * SCALE_ : -INFINITY;
        Ss[r][m1] = mask[b * M_ + m1] ? s1 * SCALE_ : -INFINITY;
    }
    __syncthreads();

    int warp = tid >> 5, lane = tid & 31;
#pragma unroll
    for (int rep = 0; rep < 2; rep++) {
        int rr = warp + rep * 8;
        float sv[8];
        float mx = -INFINITY;
#pragma unroll
        for (int j = 0; j < 8; j++) {
            sv[j] = Ss[rr][lane + j * 32];
            mx = fmaxf(mx, sv[j]);
        }
#pragma unroll
        for (int o = 16; o; o >>= 1) mx = fmaxf(mx, __shfl_xor_sync(0xffffffffu, mx, o));
        float sum = 0.0f;
#pragma unroll
        for (int j = 0; j < 8; j++) {
            float e = (mx > -INFINITY) ? __expf(sv[j] - mx) : 0.0f;
            sv[j] = e;
            sum += e;
        }
#pragma unroll
        for (int o = 16; o; o >>= 1) sum += __shfl_xor_sync(0xffffffffu, sum, o);
        float inv = (sum > 0.0f) ? (1.0f / sum) : 0.0f;
#pragma unroll
        for (int j = 0; j < 8; j++) Ss[rr][lane + j * 32] = sv[j] * inv;
    }

    int ro = tid >> 4;
    int d0 = (tid & 15) << 3;
    float acc[8] = {0, 0, 0, 0, 0, 0, 0, 0};
    for (int c0 = 0; c0 < M_; c0 += AT_MC) {
        __syncthreads();
#pragma unroll
        for (int i = 0; i < 4; i++) {
            int idx = tid * 4 + i;
            int rr = idx >> 5;
            int cc = (idx & 31) << 2;
            *(float4*)&KVs[rr][cc] =
                *(const float4*)&v[((size_t)(b * M_ + c0 + rr)) * H_ + h * HD_ + cc];
        }
        __syncthreads();
#pragma unroll
        for (int m = 0; m < AT_MC; m++) {
            float p = Ss[ro][c0 + m];
            float4 v0 = *(float4*)&KVs[m][d0];
            float4 v1 = *(float4*)&KVs[m][d0 + 4];
            acc[0] += p * v0.x; acc[1] += p * v0.y;
            acc[2] += p * v0.z; acc[3] += p * v0.w;
            acc[4] += p * v1.x; acc[5] += p * v1.y;
            acc[6] += p * v1.z; acc[7] += p * v1.w;
        }
    }
    size_t obase = ((size_t)(b * L_ + l0 + ro)) * H_ + h * HD_ + d0;
    *(float4*)&out[obase] = make_float4(acc[0], acc[1], acc[2], acc[3]);
    *(float4*)&out[obase + 4] = make_float4(acc[4], acc[5], acc[6], acc[7]);
}

// ---------------- launch --------------------------------------------------
extern "C" void kernel_launch(void* const* d_in, const int* in_sizes, int n_in,
                              void* d_out, int out_size) {
    const size_t SZ_HID = (size_t)B_ * L_ * H_;
    const size_t SZ_MEM = (size_t)B_ * M_ * H_;
    const size_t SZ_MSK = (size_t)B_ * M_;
    const size_t SZ_NRM = (size_t)H_;
    const size_t SZ_W   = (size_t)H_ * H_;

    int i_hid = 0, i_mem = 1, i_msk = 2, i_nrm = 3;
    int wi[5] = {4, 5, 6, 7, 8};
    int nw = 0;
    for (int i = 0; i < n_in; i++) {
        size_t s = (size_t)in_sizes[i];
        if (s == SZ_HID) i_hid = i;
        else if (s == SZ_MEM) i_mem = i;
        else if (s == SZ_MSK) i_msk = i;
        else if (s == SZ_NRM) i_nrm = i;
        else if (s == SZ_W && nw < 5) wi[nw++] = i;
    }
    int iq, ik, iv, io, ig;
    if (i_msk < i_mem) { ig = wi[0]; ik = wi[1]; io = wi[2]; iq = wi[3]; iv = wi[4]; }
    else               { iq = wi[0]; ik = wi[1]; iv = wi[2]; io = wi[3]; ig = wi[4]; }

    const float* hidden = (const float*)d_in[i_hid];
    const float* memtok = (const float*)d_in[i_mem];
    const void*  mraw   = d_in[i_msk];
    const float* normw  = (const float*)d_in[i_nrm];
    const float* wq = (const float*)d_in[iq];
    const float* wk = (const float*)d_in[ik];
    const float* wv = (const float*)d_in[iv];
    const float* wo = (const float*)d_in[io];
    const float* wg = (const float*)d_in[ig];
    float* out = (float*)d_out;

    float *x, *q, *g, *a, *kb, *vb;
    unsigned char* mnorm;
    cudaGetSymbolAddress((void**)&x, g_x);
    cudaGetSymbolAddress((void**)&q, g_q);
    cudaGetSymbolAddress((void**)&g, g_g);
    cudaGetSymbolAddress((void**)&a, g_a);
    cudaGetSymbolAddress((void**)&kb, g_k);
    cudaGetSymbolAddress((void**)&vb, g_v);
    cudaGetSymbolAddress((void**)&mnorm, g_mask);

    mask_normalize_kernel<<<1, 256>>>(mraw, mnorm);
    rmsnorm_kernel<<<B_ * L_, 256>>>(hidden, normw, x);

    dim3 gbig(H_ / TBN, (B_ * L_) / TBM);
    dim3 gsmall(H_ / TBN, (B_ * M_) / TBM);

    gemm_tf32_nt<<<gbig, 256>>>(x, wq, q, nullptr, B_ * L_, H_, H_);
    gemm_tf32_nt<<<gsmall, 256>>>(memtok, wk, kb, nullptr, B_ * M_, H_, H_);
    gemm_tf32_nt<<<gsmall, 256>>>(memtok, wv, vb, nullptr, B_ * M_, H_, H_);
    gemm_tf32_nt<<<gbig, 256>>>(x, wg, g, nullptr, B_ * L_, H_, H_);

    attn_kernel<<<dim3(L_ / AT_TL, NH_, B_), 256>>>(q, kb, vb, mnorm, a);

    gemm_tf32_nt<<<gbig, 256>>>(a, wo, out, g, B_ * L_, H_, H_);
}

// round 6
// speedup vs baseline: 1.1172x; 1.0043x over previous
#include <cuda_runtime.h>
#include <math.h>
#include <stdint.h>

// MemoryCrossAttention: B=4, L=4096, M=256, H=2048, NH=16, HD=128
// Round-4: cp.async double-buffered tf32 GEMM pipeline (2-stage), tf32 cvt
// moved to fragment load, 2 CTAs/SM. Attention/rmsnorm unchanged from R3.

#define B_  4
#define L_  4096
#define M_  256
#define H_  2048
#define NH_ 16
#define HD_ 128
#define EPS_ 1e-6f
#define SCALE_ 0.08838834764831845f   // HD^-0.5

// ---------------- scratch (static __device__, no allocations) ----------------
__device__ float g_x[(size_t)B_ * L_ * H_];
__device__ float g_q[(size_t)B_ * L_ * H_];
__device__ float g_g[(size_t)B_ * L_ * H_];
__device__ float g_a[(size_t)B_ * L_ * H_];
__device__ float g_k[(size_t)B_ * M_ * H_];
__device__ float g_v[(size_t)B_ * M_ * H_];
__device__ unsigned char g_mask[B_ * M_];

// ---------------- helpers ----------------------------------------------------
__device__ __forceinline__ uint32_t f2tf32(float v) {
    uint32_t r;
    asm("cvt.rna.tf32.f32 %0, %1;" : "=r"(r) : "f"(v));
    return r;
}

__device__ __forceinline__ void mma_tf32(float c[4], const uint32_t a[4],
                                         const uint32_t b[2]) {
    asm volatile(
        "mma.sync.aligned.m16n8k8.row.col.f32.tf32.tf32.f32 "
        "{%0,%1,%2,%3}, {%4,%5,%6,%7}, {%8,%9}, {%0,%1,%2,%3};"
        : "+f"(c[0]), "+f"(c[1]), "+f"(c[2]), "+f"(c[3])
        : "r"(a[0]), "r"(a[1]), "r"(a[2]), "r"(a[3]), "r"(b[0]), "r"(b[1]));
}

__device__ __forceinline__ void cp16(void* smem_dst, const void* gptr) {
    uint32_t s = (uint32_t)__cvta_generic_to_shared(smem_dst);
    asm volatile("cp.async.cg.shared.global [%0], [%1], 16;\n"
                 :: "r"(s), "l"(gptr));
}
__device__ __forceinline__ void cp_commit() {
    asm volatile("cp.async.commit_group;\n");
}
template <int N>
__device__ __forceinline__ void cp_wait() {
    asm volatile("cp.async.wait_group %0;\n" :: "n"(N));
}

// ---------------- mask normalize: detect dtype, write u8 ---------------------
__global__ __launch_bounds__(256) void mask_normalize_kernel(
    const void* __restrict__ mraw, unsigned char* __restrict__ mout) {
    const uint32_t* w = (const uint32_t*)mraw;
    int tid = threadIdx.x;
    uint32_t word = w[tid];
    int big = 0, odd = 0;
#pragma unroll
    for (int byi = 0; byi < 4; byi++) {
        uint32_t by = (word >> (byi * 8)) & 0xffu;
        if (by > 1u) big = 1;
        if (byi != 0 && by != 0u) odd = 1;
    }
    int any_big = __syncthreads_or(big);
    int any_odd = __syncthreads_or(odd);
#pragma unroll
    for (int i = 0; i < 4; i++) {
        int m = tid * 4 + i;
        unsigned char val;
        if (any_big)      val = (((const float*)mraw)[m] != 0.0f) ? 1 : 0;
        else if (any_odd) val = ((const unsigned char*)mraw)[m] ? 1 : 0;
        else              val = (((const int*)mraw)[m] != 0) ? 1 : 0;
        mout[m] = val;
    }
}

// ---------------- rmsnorm ----------------------------------------------------
__global__ __launch_bounds__(256) void rmsnorm_kernel(
    const float* __restrict__ in, const float* __restrict__ w,
    float* __restrict__ out) {
    size_t row = blockIdx.x;
    const float* x = in + row * H_;
    float* y = out + row * H_;
    int tid = threadIdx.x;

    float4 a = *(const float4*)&x[tid * 4];
    float4 b = *(const float4*)&x[1024 + tid * 4];
    float ss = a.x * a.x + a.y * a.y + a.z * a.z + a.w * a.w
             + b.x * b.x + b.y * b.y + b.z * b.z + b.w * b.w;
#pragma unroll
    for (int o = 16; o; o >>= 1) ss += __shfl_xor_sync(0xffffffffu, ss, o);
    __shared__ float sw[8];
    if ((tid & 31) == 0) sw[tid >> 5] = ss;
    __syncthreads();
    float tot = sw[0] + sw[1] + sw[2] + sw[3] + sw[4] + sw[5] + sw[6] + sw[7];
    float inv = rsqrtf(tot * (1.0f / H_) + EPS_);

    float4 wa = *(const float4*)&w[tid * 4];
    float4 wb = *(const float4*)&w[1024 + tid * 4];
    a.x *= inv * wa.x; a.y *= inv * wa.y; a.z *= inv * wa.z; a.w *= inv * wa.w;
    b.x *= inv * wb.x; b.y *= inv * wb.y; b.z *= inv * wb.z; b.w *= inv * wb.w;
    *(float4*)&y[tid * 4] = a;
    *(float4*)&y[1024 + tid * 4] = b;
}

// ---------------- tf32 GEMM with cp.async double buffering -------------------
// C[M,N] = A[M,K] @ B[N,K]^T. Block 128x128, 8 warps (2x4), warp 64x32.
// Smem holds raw fp32 (cp.async); cvt to tf32 at fragment load.
#define TBM 128
#define TBN 128
#define TBK 16
#define TST 20   // row stride in words (16 + 4 pad): conflict-free frag reads

__global__ __launch_bounds__(256, 2) void gemm_tf32_nt(
    const float* __restrict__ A, const float* __restrict__ Bm,
    float* __restrict__ C, const float* __restrict__ G,
    int M, int N, int K) {
    __shared__ float As[2][TBM][TST];
    __shared__ float Bs[2][TBN][TST];
    int bm = blockIdx.y * TBM;
    int bn = blockIdx.x * TBN;
    int tid = threadIdx.x;
    int lane = tid & 31;
    int warp = tid >> 5;
    int wm = warp >> 2;
    int wn = warp & 3;

    float acc[4][4][4];
#pragma unroll
    for (int i = 0; i < 4; i++)
#pragma unroll
        for (int j = 0; j < 4; j++)
#pragma unroll
            for (int t = 0; t < 4; t++) acc[i][j][t] = 0.0f;

    int lq = lane & 3;
    int lg = lane >> 2;

    // Per-thread load coords: 2 x 16B chunks of A and of B per tile.
    int r0 = (tid * 2) >> 2;          // row of chunk 0
    int c0q = ((tid * 2) & 3) << 2;   // k-quad of chunk 0
    int r1 = (tid * 2 + 1) >> 2;
    int c1q = ((tid * 2 + 1) & 3) << 2;

    const int nt = K / TBK;

    // Prefetch tile 0 into stage 0.
    {
        cp16(&As[0][r0][c0q], &A[(size_t)(bm + r0) * K + c0q]);
        cp16(&Bs[0][r0][c0q], &Bm[(size_t)(bn + r0) * K + c0q]);
        cp16(&As[0][r1][c1q], &A[(size_t)(bm + r1) * K + c1q]);
        cp16(&Bs[0][r1][c1q], &Bm[(size_t)(bn + r1) * K + c1q]);
        cp_commit();
    }

    for (int t = 0; t < nt; t++) {
        int cur = t & 1;
        if (t + 1 < nt) {
            int nxt = (t + 1) & 1;
            int k0 = (t + 1) * TBK;
            cp16(&As[nxt][r0][c0q], &A[(size_t)(bm + r0) * K + k0 + c0q]);
            cp16(&Bs[nxt][r0][c0q], &Bm[(size_t)(bn + r0) * K + k0 + c0q]);
            cp16(&As[nxt][r1][c1q], &A[(size_t)(bm + r1) * K + k0 + c1q]);
            cp16(&Bs[nxt][r1][c1q], &Bm[(size_t)(bn + r1) * K + k0 + c1q]);
            cp_commit();
            cp_wait<1>();   // current tile complete; next still in flight
        } else {
            cp_wait<0>();
        }
        __syncthreads();

#pragma unroll
        for (int kk = 0; kk < TBK; kk += 8) {
            uint32_t af[4][4];
            uint32_t bf[4][2];
#pragma unroll
            for (int am = 0; am < 4; am++) {
                int r = wm * 64 + am * 16 + lg;
                af[am][0] = f2tf32(As[cur][r][kk + lq]);
                af[am][1] = f2tf32(As[cur][r + 8][kk + lq]);
                af[am][2] = f2tf32(As[cur][r][kk + lq + 4]);
                af[am][3] = f2tf32(As[cur][r + 8][kk + lq + 4]);
            }
#pragma unroll
            for (int bj = 0; bj < 4; bj++) {
                int cidx = wn * 32 + bj * 8 + lg;
                bf[bj][0] = f2tf32(Bs[cur][cidx][kk + lq]);
                bf[bj][1] = f2tf32(Bs[cur][cidx][kk + lq + 4]);
            }
#pragma unroll
            for (int am = 0; am < 4; am++)
#pragma unroll
                for (int bj = 0; bj < 4; bj++)
                    mma_tf32(acc[am][bj], af[am], bf[bj]);
        }
        __syncthreads();   // stage `cur` free for reuse at t+2
    }

#pragma unroll
    for (int am = 0; am < 4; am++) {
        size_t row0 = (size_t)(bm + wm * 64 + am * 16 + lg);
#pragma unroll
        for (int bj = 0; bj < 4; bj++) {
            size_t col = (size_t)(bn + wn * 32 + bj * 8 + lq * 2);
            float2 p0 = make_float2(acc[am][bj][0], acc[am][bj][1]);
            float2 p1 = make_float2(acc[am][bj][2], acc[am][bj][3]);
            if (G != nullptr) {
                float2 g0 = *(const float2*)&G[row0 * (size_t)N + col];
                float2 g1 = *(const float2*)&G[(row0 + 8) * (size_t)N + col];
                p0.x *= 1.0f / (1.0f + __expf(-g0.x));
                p0.y *= 1.0f / (1.0f + __expf(-g0.y));
                p1.x *= 1.0f / (1.0f + __expf(-g1.x));
                p1.y *= 1.0f / (1.0f + __expf(-g1.y));
            }
            *(float2*)&C[row0 * (size_t)N + col] = p0;
            *(float2*)&C[(row0 + 8) * (size_t)N + col] = p1;
        }
    }
}

// ---------------- attention: per (b,h), 16 L-rows per block ------------------
#define AT_TL 16
#define AT_MC 32

__global__ __launch_bounds__(256) void attn_kernel(
    const float* __restrict__ q, const float* __restrict__ k,
    const float* __restrict__ v, const unsigned char* __restrict__ mask,
    float* __restrict__ out) {
    __shared__ float Qs[AT_TL][HD_ + 4];
    __shared__ float KVs[AT_MC][HD_ + 4];
    __shared__ float Ss[AT_TL][M_];

    int b = blockIdx.z;
    int h = blockIdx.y;
    int l0 = blockIdx.x * AT_TL;
    int tid = threadIdx.x;

#pragma unroll
    for (int i = 0; i < 2; i++) {
        int idx = tid * 2 + i;
        int r = idx >> 5;
        int c = (idx & 31) << 2;
        *(float4*)&Qs[r][c] =
            *(const float4*)&q[((size_t)(b * L_ + l0 + r)) * H_ + h * HD_ + c];
    }

    int r = tid & 15;
    int mg = tid >> 4;
    for (int c0 = 0; c0 < M_; c0 += AT_MC) {
        __syncthreads();
#pragma unroll
        for (int i = 0; i < 4; i++) {
            int idx = tid * 4 + i;
            int rr = idx >> 5;
            int cc = (idx & 31) << 2;
            *(float4*)&KVs[rr][cc] =
                *(const float4*)&k[((size_t)(b * M_ + c0 + rr)) * H_ + h * HD_ + cc];
        }
        __syncthreads();
        float s0 = 0.0f, s1 = 0.0f;
#pragma unroll
        for (int d = 0; d < HD_; d += 4) {
            float4 qv = *(float4*)&Qs[r][d];
            float4 k0v = *(float4*)&KVs[mg][d];
            float4 k1v = *(float4*)&KVs[mg + 16][d];
            s0 += qv.x * k0v.x + qv.y * k0v.y + qv.z * k0v.z + qv.w * k0v.w;
            s1 += qv.x * k1v.x + qv.y * k1v.y + qv.z * k1v.z + qv.w * k1v.w;
        }
        int m0 = c0 + mg, m1 = c0 + mg + 16;
        Ss[r][m0] = mask[b * M_ + m0] ? s0 * SCALE_ : -INFINITY;
        Ss[r][m1] = mask[b * M_ + m1] ? s1 * SCALE_ : -INFINITY;
    }
    __syncthreads();

    int warp = tid >> 5, lane = tid & 31;
#pragma unroll
    for (int rep = 0; rep < 2; rep++) {
        int rr = warp + rep * 8;
        float sv[8];
        float mx = -INFINITY;
#pragma unroll
        for (int j = 0; j < 8; j++) {
            sv[j] = Ss[rr][lane + j * 32];
            mx = fmaxf(mx, sv[j]);
        }
#pragma unroll
        for (int o = 16; o; o >>= 1) mx = fmaxf(mx, __shfl_xor_sync(0xffffffffu, mx, o));
        float sum = 0.0f;
#pragma unroll
        for (int j = 0; j < 8; j++) {
            float e = (mx > -INFINITY) ? __expf(sv[j] - mx) : 0.0f;
            sv[j] = e;
            sum += e;
        }
#pragma unroll
        for (int o = 16; o; o >>= 1) sum += __shfl_xor_sync(0xffffffffu, sum, o);
        float inv = (sum > 0.0f) ? (1.0f / sum) : 0.0f;
#pragma unroll
        for (int j = 0; j < 8; j++) Ss[rr][lane + j * 32] = sv[j] * inv;
    }

    int ro = tid >> 4;
    int d0 = (tid & 15) << 3;
    float acc[8] = {0, 0, 0, 0, 0, 0, 0, 0};
    for (int c0 = 0; c0 < M_; c0 += AT_MC) {
        __syncthreads();
#pragma unroll
        for (int i = 0; i < 4; i++) {
            int idx = tid * 4 + i;
            int rr = idx >> 5;
            int cc = (idx & 31) << 2;
            *(float4*)&KVs[rr][cc] =
                *(const float4*)&v[((size_t)(b * M_ + c0 + rr)) * H_ + h * HD_ + cc];
        }
        __syncthreads();
#pragma unroll
        for (int m = 0; m < AT_MC; m++) {
            float p = Ss[ro][c0 + m];
            float4 v0 = *(float4*)&KVs[m][d0];
            float4 v1 = *(float4*)&KVs[m][d0 + 4];
            acc[0] += p * v0.x; acc[1] += p * v0.y;
            acc[2] += p * v0.z; acc[3] += p * v0.w;
            acc[4] += p * v1.x; acc[5] += p * v1.y;
            acc[6] += p * v1.z; acc[7] += p * v1.w;
        }
    }
    size_t obase = ((size_t)(b * L_ + l0 + ro)) * H_ + h * HD_ + d0;
    *(float4*)&out[obase] = make_float4(acc[0], acc[1], acc[2], acc[3]);
    *(float4*)&out[obase + 4] = make_float4(acc[4], acc[5], acc[6], acc[7]);
}

// ---------------- launch --------------------------------------------------
extern "C" void kernel_launch(void* const* d_in, const int* in_sizes, int n_in,
                              void* d_out, int out_size) {
    const size_t SZ_HID = (size_t)B_ * L_ * H_;
    const size_t SZ_MEM = (size_t)B_ * M_ * H_;
    const size_t SZ_MSK = (size_t)B_ * M_;
    const size_t SZ_NRM = (size_t)H_;
    const size_t SZ_W   = (size_t)H_ * H_;

    int i_hid = 0, i_mem = 1, i_msk = 2, i_nrm = 3;
    int wi[5] = {4, 5, 6, 7, 8};
    int nw = 0;
    for (int i = 0; i < n_in; i++) {
        size_t s = (size_t)in_sizes[i];
        if (s == SZ_HID) i_hid = i;
        else if (s == SZ_MEM) i_mem = i;
        else if (s == SZ_MSK) i_msk = i;
        else if (s == SZ_NRM) i_nrm = i;
        else if (s == SZ_W && nw < 5) wi[nw++] = i;
    }
    int iq, ik, iv, io, ig;
    if (i_msk < i_mem) { ig = wi[0]; ik = wi[1]; io = wi[2]; iq = wi[3]; iv = wi[4]; }
    else               { iq = wi[0]; ik = wi[1]; iv = wi[2]; io = wi[3]; ig = wi[4]; }

    const float* hidden = (const float*)d_in[i_hid];
    const float* memtok = (const float*)d_in[i_mem];
    const void*  mraw   = d_in[i_msk];
    const float* normw  = (const float*)d_in[i_nrm];
    const float* wq = (const float*)d_in[iq];
    const float* wk = (const float*)d_in[ik];
    const float* wv = (const float*)d_in[iv];
    const float* wo = (const float*)d_in[io];
    const float* wg = (const float*)d_in[ig];
    float* out = (float*)d_out;

    float *x, *q, *g, *a, *kb, *vb;
    unsigned char* mnorm;
    cudaGetSymbolAddress((void**)&x, g_x);
    cudaGetSymbolAddress((void**)&q, g_q);
    cudaGetSymbolAddress((void**)&g, g_g);
    cudaGetSymbolAddress((void**)&a, g_a);
    cudaGetSymbolAddress((void**)&kb, g_k);
    cudaGetSymbolAddress((void**)&vb, g_v);
    cudaGetSymbolAddress((void**)&mnorm, g_mask);

    mask_normalize_kernel<<<1, 256>>>(mraw, mnorm);
    rmsnorm_kernel<<<B_ * L_, 256>>>(hidden, normw, x);

    dim3 gbig(H_ / TBN, (B_ * L_) / TBM);
    dim3 gsmall(H_ / TBN, (B_ * M_) / TBM);

    gemm_tf32_nt<<<gbig, 256>>>(x, wq, q, nullptr, B_ * L_, H_, H_);
    gemm_tf32_nt<<<gsmall, 256>>>(memtok, wk, kb, nullptr, B_ * M_, H_, H_);
    gemm_tf32_nt<<<gsmall, 256>>>(memtok, wv, vb, nullptr, B_ * M_, H_, H_);
    gemm_tf32_nt<<<gbig, 256>>>(x, wg, g, nullptr, B_ * L_, H_, H_);

    attn_kernel<<<dim3(L_ / AT_TL, NH_, B_), 256>>>(q, kb, vb, mnorm, a);

    gemm_tf32_nt<<<gbig, 256>>>(a, wo, out, g, B_ * L_, H_, H_);
}